// round 10
// baseline (speedup 1.0000x reference)
#include <cuda_runtime.h>
#include <math.h>

#define BB 4
#define HH 64
#define WW 64
#define CC 128
#define PP 4096
#define SPLITS 3
#define LOG2E 1.44269504088896340736f

// ---------------- static scratch ----------------
__device__ float g_x[BB * PP * 2];                    // per-pixel (mean, max)
__device__ __align__(16) float g_q[BB * PP * 48];     // query hi[0..23] lo[24..47], *LOG2E, tf32-split
__device__ float g_M[BB * PP];                        // M2 = patch L2 norm * LOG2E
__device__ __align__(16) float g_w[BB * PP * 48];     // compacted key hi/lo (normalized), tf32-split
__device__ __align__(16) float g_tap[BB * PP * 16];   // compacted taps [t0..t8, 1.0, 0 x6]
__device__ float g_sig[BB * PP];                      // sigmoid(gate conv)
__device__ int   g_vrank[PP];
__device__ int   g_need[PP];
__device__ int   g_counts[2];                         // [0]=n_valid, [1]=n_need
__device__ float g_pf[(size_t)BB * SPLITS * PP * 16]; // split partials [cols 0..8 taps, 9 = l]
__device__ float g_tmp9[BB * PP * 9];
__device__ int   g_cnt[BB * 64];                      // arrival counters (self-resetting)

__device__ __forceinline__ float ex2f(float x) {
    float r; asm("ex2.approx.f32 %0, %1;" : "=f"(r) : "f"(x)); return r;
}
__device__ __forceinline__ unsigned cvt_tf32(float f) {
    unsigned u; asm("cvt.rna.tf32.f32 %0, %1;" : "=r"(u) : "f"(f)); return u;
}
#define MMA4(c0,c1,c2,c3,a0,a1,a2,a3,b0,b1) \
    asm volatile("mma.sync.aligned.m16n8k8.row.col.f32.tf32.tf32.f32 " \
        "{%0,%1,%2,%3}, {%4,%5,%6,%7}, {%8,%9}, {%0,%1,%2,%3};" \
        : "+f"(c0), "+f"(c1), "+f"(c2), "+f"(c3) \
        : "r"(a0), "r"(a1), "r"(a2), "r"(a3), "r"(b0), "r"(b1))

// ---------------- KA: mean/max (blocks 0..2047) + compaction+vrank (block 2048) ----------------
__global__ void kA(const float* __restrict__ inp, const float* __restrict__ mask) {
    __shared__ int wv[8], wn_[8];
    if (blockIdx.x == 2048) {
        int t = threadIdx.x;
        int lane = t & 31, wid = t >> 5;
        unsigned fv = 0, fn = 0;
        int cv = 0, cn = 0;
        int base_p = t * 16;
        for (int i = 0; i < 16; i++) {
            int p = base_p + i, y = p >> 6, x = p & 63;
            int allone = 1, anyz = 0;
            #pragma unroll
            for (int dy = -1; dy <= 1; dy++)
                #pragma unroll
                for (int dx = -1; dx <= 1; dx++) {
                    int yy = y + dy, xx = x + dx;
                    if (yy < 0 || yy >= HH || xx < 0 || xx >= WW) {
                        allone = 0;
                    } else {
                        float mv = mask[(yy << 6) + xx];
                        if (mv < 0.5f) { allone = 0; anyz = 1; }
                    }
                }
            if (allone) { fv |= (1u << i); cv++; }
            if (anyz)   { fn |= (1u << i); cn++; }
        }
        int iv = cv, inn = cn;
        #pragma unroll
        for (int o = 1; o < 32; o <<= 1) {
            int a = __shfl_up_sync(0xffffffffu, iv, o);
            int b = __shfl_up_sync(0xffffffffu, inn, o);
            if (lane >= o) { iv += a; inn += b; }
        }
        if (lane == 31) { wv[wid] = iv; wn_[wid] = inn; }
        __syncthreads();
        int bv = 0, bn = 0;
        for (int i = 0; i < wid; i++) { bv += wv[i]; bn += wn_[i]; }
        int offv = bv + iv - cv;
        int offn = bn + inn - cn;
        for (int i = 0; i < 16; i++) {
            int p = base_p + i;
            if (fv & (1u << i)) g_vrank[p] = offv++;
            else                g_vrank[p] = -1;
            if (fn & (1u << i)) g_need[offn++] = p;
        }
        if (t == 255) { g_counts[0] = bv + iv; g_counts[1] = bn + inn; }
        return;
    }
    int warp = blockIdx.x * 8 + (threadIdx.x >> 5);
    int lane = threadIdx.x & 31;
    const float4* base = (const float4*)(inp + (size_t)warp * CC);
    float4 v = base[lane];
    float s = (v.x + v.y) + (v.z + v.w);
    float m = fmaxf(fmaxf(v.x, v.y), fmaxf(v.z, v.w));
    #pragma unroll
    for (int o = 16; o; o >>= 1) {
        s += __shfl_xor_sync(0xffffffffu, s, o);
        m = fmaxf(m, __shfl_xor_sync(0xffffffffu, m, o));
    }
    if (lane == 0) {
        g_x[warp * 2 + 0] = s * (1.0f / 128.0f);
        g_x[warp * 2 + 1] = m;
    }
}

// ---------------- KB: patches + tf32 hi/lo splits + taps + gate conv ----------------
__global__ void kB_patches(const float* __restrict__ convw) {
    int idx = blockIdx.x * blockDim.x + threadIdx.x;   // BB*PP
    if (idx >= BB * PP) return;
    int p = idx & 4095, y = p >> 6, x = p & 63;
    int b = idx >> 12;
    float v[18];
    float ss = 0.f;
    int j = 0;
    #pragma unroll
    for (int kh = 0; kh < 3; kh++)
        #pragma unroll
        for (int kw = 0; kw < 3; kw++) {
            int yy = y + kh - 1, xx = x + kw - 1;
            float a = 0.f, c1 = 0.f;
            if (yy >= 0 && yy < HH && xx >= 0 && xx < WW) {
                int q = (b << 12) + (yy << 6) + xx;
                a  = g_x[q * 2 + 0];
                c1 = g_x[q * 2 + 1];
            }
            v[j] = a; v[j + 1] = c1;
            ss += a * a + c1 * c1;
            j += 2;
        }
    float Mn = sqrtf(ss);
    // query: scaled by LOG2E, split into tf32 hi + fp32 lo
    float* dq = g_q + (size_t)idx * 48;
    #pragma unroll
    for (int i = 0; i < 18; i++) {
        float val = v[i] * LOG2E;
        float h = __uint_as_float(cvt_tf32(val));
        dq[i] = h;
        dq[24 + i] = val - h;
    }
    #pragma unroll
    for (int i = 18; i < 24; i++) { dq[i] = 0.f; dq[24 + i] = 0.f; }
    g_M[idx] = Mn * LOG2E;
    // key/value if fully-valid patch
    int vr = g_vrank[p];
    if (vr >= 0) {
        float rn = 1.f / fmaxf(Mn, 1e-4f);
        float* dw = g_w + (size_t)((b << 12) + vr) * 48;
        #pragma unroll
        for (int i = 0; i < 18; i++) {
            float wv = v[i] * rn;
            float h = __uint_as_float(cvt_tf32(wv));
            dw[i] = h;
            dw[24 + i] = wv - h;
        }
        #pragma unroll
        for (int i = 18; i < 24; i++) { dw[i] = 0.f; dw[24 + i] = 0.f; }
        float* dt = g_tap + (size_t)((b << 12) + vr) * 16;
        #pragma unroll
        for (int k = 0; k < 9; k++) dt[k] = v[2 * k];
        dt[9] = 1.0f;                       // denominator column
        #pragma unroll
        for (int k = 10; k < 16; k++) dt[k] = 0.f;
    }
    // 7x7x2 gate conv + sigmoid
    float gg = 0.f;
    #pragma unroll
    for (int u = 0; u < 7; u++) {
        int yy = y + u - 3;
        if (yy < 0 || yy >= HH) continue;
        #pragma unroll
        for (int vv = 0; vv < 7; vv++) {
            int xx = x + vv - 3;
            if (xx < 0 || xx >= WW) continue;
            int qq = (b << 12) + (yy << 6) + xx;
            gg += g_x[qq * 2 + 0] * __ldg(convw + (u * 7 + vv) * 2 + 0)
                + g_x[qq * 2 + 1] * __ldg(convw + (u * 7 + vv) * 2 + 1);
        }
    }
    g_sig[idx] = 1.f / (1.f + __expf(-gg));
}

// ---------------- KD: tensor-core attention (3xTF32 scores + TF32 value GEMM) ----------------
__global__ void __launch_bounds__(128, 4) kD_attn() {
    __shared__ __align__(16) float sW[32 * 52];   // key hi[0..23] lo[24..47], stride 52 (bank-clean)
    __shared__ __align__(16) float sT[32 * 24];   // taps [0..15], stride 24 (bank-clean)
    __shared__ int s_win;
    int nneed = g_counts[1];
    int x = blockIdx.x, b = blockIdx.y, s = blockIdx.z;
    if (x * 64 >= nneed) return;
    int nvalid = g_counts[0];
    int chunk = (nvalid + SPLITS - 1) / SPLITS;
    int v0 = s * chunk;
    int v1 = min(v0 + chunk, nvalid);
    int t = threadIdx.x;
    int warp = t >> 5, lane = t & 31;
    int g = lane >> 2, q = lane & 3;
    int rowbase = x * 64 + warp * 16;
    int r_lo = rowbase + g, r_hi = r_lo + 8;
    int n_lo = g_need[r_lo], n_hi = g_need[r_hi];

    // A fragments (queries), 3 k-chunks, hi + lo
    unsigned Ah[3][4], Al[3][4];
    {
        const unsigned* qpl = (const unsigned*)(g_q + (size_t)((b << 12) + n_lo) * 48);
        const unsigned* qph = (const unsigned*)(g_q + (size_t)((b << 12) + n_hi) * 48);
        #pragma unroll
        for (int c = 0; c < 3; c++) {
            Ah[c][0] = qpl[c * 8 + q];       Ah[c][1] = qph[c * 8 + q];
            Ah[c][2] = qpl[c * 8 + q + 4];   Ah[c][3] = qph[c * 8 + q + 4];
            Al[c][0] = qpl[24 + c * 8 + q];     Al[c][1] = qph[24 + c * 8 + q];
            Al[c][2] = qpl[24 + c * 8 + q + 4]; Al[c][3] = qph[24 + c * 8 + q + 4];
        }
    }
    float M2lo = g_M[(b << 12) + n_lo];
    float M2hi = g_M[(b << 12) + n_hi];

    float v00 = 0, v01 = 0, v02 = 0, v03 = 0;   // value accum, taps 0..7
    float v10 = 0, v11 = 0, v12 = 0, v13 = 0;   // value accum, taps 8..15 (9 = l)

    for (int base = v0; base < v1; base += 32) {
        __syncthreads();
        {   // stage 32 keys (zero-fill phantoms: taps=0 kills their contribution)
            int ks = t >> 2, part = t & 3;
            float4 z4 = make_float4(0.f, 0.f, 0.f, 0.f);
            float4* dw = (float4*)(sW + ks * 52 + part * 12);
            if (base + ks < v1) {
                const float4* sw4 = (const float4*)(g_w + (size_t)((b << 12) + base + ks) * 48 + part * 12);
                dw[0] = sw4[0]; dw[1] = sw4[1]; dw[2] = sw4[2];
            } else {
                dw[0] = z4; dw[1] = z4; dw[2] = z4;
            }
            if (t < 64) {
                int k2 = t >> 1, half = t & 1;
                float4* dt = (float4*)(sT + k2 * 24 + half * 8);
                if (base + k2 < v1) {
                    const float4* st4 = (const float4*)(g_tap + (size_t)((b << 12) + base + k2) * 16 + half * 8);
                    dt[0] = st4[0]; dt[1] = st4[1];
                } else {
                    dt[0] = z4; dt[1] = z4;
                }
            }
        }
        __syncthreads();
        const unsigned* swu = (const unsigned*)sW;
        const unsigned* stu = (const unsigned*)sT;
        #pragma unroll
        for (int kt = 0; kt < 4; kt++) {
            float d0 = 0.f, d1 = 0.f, d2 = 0.f, d3 = 0.f;
            int rowoff = (kt * 8 + g) * 52;
            #pragma unroll
            for (int c = 0; c < 3; c++) {
                unsigned bh0 = swu[rowoff + c * 8 + q];
                unsigned bh1 = swu[rowoff + c * 8 + q + 4];
                unsigned bl0 = swu[rowoff + 24 + c * 8 + q];
                unsigned bl1 = swu[rowoff + 24 + c * 8 + q + 4];
                MMA4(d0, d1, d2, d3, Ah[c][0], Ah[c][1], Ah[c][2], Ah[c][3], bh0, bh1);
                MMA4(d0, d1, d2, d3, Al[c][0], Al[c][1], Al[c][2], Al[c][3], bh0, bh1);
                MMA4(d0, d1, d2, d3, Ah[c][0], Ah[c][1], Ah[c][2], Ah[c][3], bl0, bl1);
            }
            // softmax numerator weights (score <= M always; no rescale)
            unsigned u0 = cvt_tf32(ex2f(d0 - M2lo));
            unsigned u1 = cvt_tf32(ex2f(d1 - M2lo));
            unsigned u2 = cvt_tf32(ex2f(d2 - M2hi));
            unsigned u3 = cvt_tf32(ex2f(d3 - M2hi));
            // permute D-fragment -> A-fragment (intra row-quad)
            int bq = lane & ~3;
            int qh = q >> 1;
            bool par = (q & 1) != 0;
            unsigned s00 = __shfl_sync(0xffffffffu, u0, bq + qh);
            unsigned s01 = __shfl_sync(0xffffffffu, u1, bq + qh);
            unsigned a0 = par ? s01 : s00;
            unsigned s02 = __shfl_sync(0xffffffffu, u2, bq + qh);
            unsigned s03 = __shfl_sync(0xffffffffu, u3, bq + qh);
            unsigned a1 = par ? s03 : s02;
            unsigned s10 = __shfl_sync(0xffffffffu, u0, bq + 2 + qh);
            unsigned s11 = __shfl_sync(0xffffffffu, u1, bq + 2 + qh);
            unsigned a2 = par ? s11 : s10;
            unsigned s12 = __shfl_sync(0xffffffffu, u2, bq + 2 + qh);
            unsigned s13 = __shfl_sync(0xffffffffu, u3, bq + 2 + qh);
            unsigned a3 = par ? s13 : s12;
            // value GEMM: attn[16x8] x taps[8x16]
            unsigned vb00 = stu[(kt * 8 + q) * 24 + g];
            unsigned vb01 = stu[(kt * 8 + q + 4) * 24 + g];
            unsigned vb10 = stu[(kt * 8 + q) * 24 + 8 + g];
            unsigned vb11 = stu[(kt * 8 + q + 4) * 24 + 8 + g];
            MMA4(v00, v01, v02, v03, a0, a1, a2, a3, vb00, vb01);
            MMA4(v10, v11, v12, v13, a0, a1, a2, a3, vb10, vb11);
        }
    }
    // store split partials
    if (r_lo < nneed) {
        float* pa = g_pf + (size_t)(((b * SPLITS + s) << 12) + r_lo) * 16;
        pa[2 * q] = v00; pa[2 * q + 1] = v01;
        pa[8 + 2 * q] = v10; pa[8 + 2 * q + 1] = v11;
    }
    if (r_hi < nneed) {
        float* pa = g_pf + (size_t)(((b * SPLITS + s) << 12) + r_hi) * 16;
        pa[2 * q] = v02; pa[2 * q + 1] = v03;
        pa[8 + 2 * q] = v12; pa[8 + 2 * q + 1] = v13;
    }
    __syncthreads();
    if (t == 0) {
        __threadfence();
        int old = atomicAdd(&g_cnt[b * 64 + x], 1);
        s_win = (old == SPLITS - 1) ? 1 : 0;
        if (s_win) g_cnt[b * 64 + x] = 0;    // reset for next graph replay
    }
    __syncthreads();
    if (s_win && t < 64) {
        int r = x * 64 + t;
        if (r < nneed) {
            int n = g_need[r];
            float M2v = g_M[(b << 12) + n];
            float f[10];
            #pragma unroll
            for (int k = 0; k < 10; k++) f[k] = 0.f;
            f[9] = (float)(PP - nvalid) * ex2f(-M2v);   // masked keys' denominator
            #pragma unroll
            for (int s2 = 0; s2 < SPLITS; s2++) {
                const float* pa = g_pf + (size_t)(((b * SPLITS + s2) << 12) + r) * 16;
                #pragma unroll
                for (int k = 0; k < 10; k++) f[k] += pa[k];
            }
            float rl = 1.f / f[9];
            float* dst = g_tmp9 + (size_t)((b << 12) + n) * 9;
            #pragma unroll
            for (int k = 0; k < 9; k++) dst[k] = f[k] * rl;
        }
    }
}

// ---------------- KF: transpose-conv gather + final elementwise ----------------
__global__ void kF_final(const float* __restrict__ inp, const float* __restrict__ mask,
                         const float* __restrict__ bias, float* __restrict__ out) {
    int gw = blockIdx.x * 8 + (threadIdx.x >> 5);
    int lane = threadIdx.x & 31;
    int b = gw >> 12, p = gw & 4095, y = p >> 6, x = p & 63;
    float mv = mask[p];
    float ysum = 0.f;
    if (mv < 0.5f && lane < 9) {
        int kh = lane / 3, kw = lane % 3;
        int ny = y - (kh - 1), nx = x - (kw - 1);
        if (ny >= 0 && ny < HH && nx >= 0 && nx < WW)
            ysum = g_tmp9[(size_t)((b << 12) + (ny << 6) + nx) * 9 + lane];
    }
    #pragma unroll
    for (int o = 16; o; o >>= 1)
        ysum += __shfl_xor_sync(0xffffffffu, ysum, o);
    float sg = g_sig[gw];
    float yb = ysum * 0.25f;
    float w = 1.0f - mv;
    int i4 = (gw << 5) + lane;
    float4 iv = ((const float4*)inp)[i4];
    float4 bv = ((const float4*)bias)[(p << 5) + lane];
    float4 o4;
    o4.x = sg * (iv.x + (yb + bv.x) * w);
    o4.y = sg * (iv.y + (yb + bv.y) * w);
    o4.z = sg * (iv.z + (yb + bv.z) * w);
    o4.w = sg * (iv.w + (yb + bv.w) * w);
    ((float4*)out)[i4] = o4;
}

// ---------------- launch ----------------
extern "C" void kernel_launch(void* const* d_in, const int* in_sizes, int n_in,
                              void* d_out, int out_size) {
    const float* inp   = (const float*)d_in[0];
    const float* mask  = (const float*)d_in[1];
    const float* bias  = (const float*)d_in[2];
    const float* convw = (const float*)d_in[3];
    float* out = (float*)d_out;

    kA<<<2049, 256>>>(inp, mask);
    kB_patches<<<(BB * PP) / 256, 256>>>(convw);
    dim3 gD(64, BB, SPLITS);
    kD_attn<<<gD, 128>>>();
    kF_final<<<(BB * PP) / 8, 256>>>(inp, mask, bias, out);
}